// round 5
// baseline (speedup 1.0000x reference)
#include <cuda_runtime.h>
#include <cstdint>

// SemiConv2d: 5x5 max-plus dilation, 'same' padding with -inf.
// input:  (16, 64, 256, 256) fp32 -> 1024 independent 256x256 images
// kernel: (5, 5) fp32
//
// Row-streaming, 5 rotating accumulator slots, 4 cols/thread (float4 I/O).
// R4 change: SINGLE BALANCED WAVE. 128-row strips -> 4096 warp-tasks over
// 1024 blocks x 128 threads = 4096 warps, all co-resident (27.7 warps/SM,
// regs=44 allows 46/SM). Eliminates the ~37% ragged-second-wave idle that
// capped issue at 66%. Also amortizes the 4 warm-up steps over 128 stored
// rows instead of 64 (-3% work).

#define IMG_H 256
#define IMG_W 256

__device__ __align__(16) float g_ninf[16];

__global__ void fill_ninf_kernel() {
    g_ninf[threadIdx.x] = __int_as_float(0xff800000u);
}

__global__ void __launch_bounds__(128) dil5x5_kernel(
    const float* __restrict__ x,
    const float* __restrict__ kw,
    float* __restrict__ out)
{
    const int lane   = threadIdx.x & 31;
    const int wlocal = threadIdx.x >> 5;
    const int w      = blockIdx.x * 4 + wlocal;   // warp-task id, 0..4095

    const int img   = w >> 2;          // 0..1023
    const int strip = (w >> 1) & 1;    // 0..1  -> 128-row strip
    const int half  = w & 1;           // 0..1  -> 128-col half

    const int i0 = strip << 7;                    // first output row of strip
    const int j0 = (half << 7) + (lane << 2);     // first of 4 output cols

    float k[25];
#pragma unroll
    for (int t = 0; t < 25; ++t) k[t] = kw[t];

    const float NI = __int_as_float(0xff800000u);

    float acc[5][4];
#pragma unroll
    for (int q = 0; q < 5; ++q)
#pragma unroll
        for (int c = 0; c < 4; ++c) acc[q][c] = NI;

    const float* xim = x   + (size_t)img * (IMG_H * IMG_W);
    float*       oim = out + (size_t)img * (IMG_H * IMG_W);

    // Loop-invariant column-halo validity. A covers cols j0-4..j0-1 (we use
    // j0-2,j0-1): invalid only when j0==0. C covers j0+4..j0+7 (we use
    // j0+4,j0+5): invalid only when j0==252. B (j0..j0+3) always valid.
    const bool c0ok = (j0 != 0);
    const bool c2ok = (j0 != 252);

    const float4 NIV = make_float4(NI, NI, NI, NI);
    float4 A = NIV, B = NIV, C = NIV;   // A/C stay -inf forever on edge lanes

    const float* ninf = g_ninf;         // 16 floats of -inf

    int r = i0 - 2;                                         // input row
    const float* rowptr = xim + (ptrdiff_t)r * IMG_W + (j0 - 4);
    float* optr = oim + (size_t)i0 * IMG_W + j0;

    // Step s (0..131): consume input row r = i0+s-2 (or the -inf row when r
    // is outside the image), emit output row r-2 = i0+s-4 once s>=4.
#define DO_STEP(PH)                                                          \
    {                                                                        \
        const bool vok = ((unsigned)r) < (unsigned)IMG_H;                    \
        const float* rp = vok ? rowptr : ninf;                               \
        if (c0ok) A = *(const float4*)(rp);                                  \
        B = *(const float4*)(rp + 4);                                        \
        if (c2ok) C = *(const float4*)(rp + 8);                              \
        float X[12] = {A.x, A.y, A.z, A.w,                                   \
                       B.x, B.y, B.z, B.w,                                   \
                       C.x, C.y, C.z, C.w};                                  \
        _Pragma("unroll")                                                    \
        for (int q = 0; q < 5; ++q) {                                        \
            const int d = (q - (PH) + 5) % 5;   /* compile-time */           \
            const int u = 4 - d;                /* kernel row   */           \
            if (d == 4) {                                                    \
                _Pragma("unroll")                                            \
                for (int c = 0; c < 4; ++c)                                  \
                    acc[q][c] = X[c + 2] + k[u * 5 + 0];                     \
                _Pragma("unroll")                                            \
                for (int v = 1; v < 5; ++v)                                  \
                    _Pragma("unroll")                                        \
                    for (int c = 0; c < 4; ++c)                              \
                        acc[q][c] = fmaxf(acc[q][c], X[c + v + 2] + k[u * 5 + v]); \
            } else {                                                         \
                _Pragma("unroll")                                            \
                for (int v = 0; v < 5; ++v)                                  \
                    _Pragma("unroll")                                        \
                    for (int c = 0; c < 4; ++c)                              \
                        acc[q][c] = fmaxf(acc[q][c], X[c + v + 2] + k[u * 5 + v]); \
            }                                                                \
        }                                                                    \
        if (r >= i0 + 2) {                                                   \
            *(float4*)optr = make_float4(acc[PH][0], acc[PH][1],             \
                                         acc[PH][2], acc[PH][3]);            \
            optr += IMG_W;                                                   \
        }                                                                    \
        ++r;                                                                 \
        rowptr += IMG_W;                                                     \
    }

    // 132 steps total: 26 x 5 phases (s=0..129) + phases 0,1 (s=130,131).
    for (int sb = 0; sb < 26; ++sb) {
        DO_STEP(0) DO_STEP(1) DO_STEP(2) DO_STEP(3) DO_STEP(4)
    }
    DO_STEP(0) DO_STEP(1)
#undef DO_STEP
}

extern "C" void kernel_launch(void* const* d_in, const int* in_sizes, int n_in,
                              void* d_out, int out_size) {
    const float* x  = (const float*)d_in[0];  // (16,64,256,256)
    const float* kw = (const float*)d_in[1];  // (5,5)
    float* out = (float*)d_out;
    fill_ninf_kernel<<<1, 16>>>();
    // 4096 warp-tasks = 1024 images x 2 row-strips x 2 column-halves,
    // 1024 blocks x 4 warps = one balanced resident wave.
    dil5x5_kernel<<<1024, 128>>>(x, kw, out);
}

// round 6
// speedup vs baseline: 1.2381x; 1.2381x over previous
#include <cuda_runtime.h>
#include <cstdint>

// SemiConv2d: 5x5 max-plus dilation, 'same' padding with -inf.
// input:  (16, 64, 256, 256) fp32 -> 1024 independent 256x256 images
// kernel: (5, 5) fp32
//
// Row-streaming, 5 rotating accumulator slots, 4 cols/thread (float4 I/O).
// R5 change: SOFTWARE PREFETCH with compile-time double buffering.
// Each step issues the NEXT row's 3 loads before doing the current row's
// ~196 math ops, converting synchronized load->use stalls (which capped
// issue at ~63%) into fully covered latency. Buffer parity is baked into a
// 10-step unroll (LCM of 2 buffers x 5 phase slots) -> zero swap MOVs.
// Grid: back to the measured-best 2048 blocks x 128 thr, 64-row strips.

#define IMG_H 256
#define IMG_W 256

__device__ __align__(16) float g_ninf[16];

__global__ void fill_ninf_kernel() {
    g_ninf[threadIdx.x] = __int_as_float(0xff800000u);
}

__global__ void __launch_bounds__(128) dil5x5_kernel(
    const float* __restrict__ x,
    const float* __restrict__ kw,
    float* __restrict__ out)
{
    const int lane   = threadIdx.x & 31;
    const int wlocal = threadIdx.x >> 5;
    const int w      = blockIdx.x * 4 + wlocal;   // warp-task id, 0..8191

    const int img   = w >> 3;          // 0..1023
    const int strip = (w >> 1) & 3;    // 0..3  -> 64-row strip
    const int half  = w & 1;           // 0..1  -> 128-col half

    const int i0 = strip << 6;                    // first output row of strip
    const int j0 = (half << 7) + (lane << 2);     // first of 4 output cols

    float k[25];
#pragma unroll
    for (int t = 0; t < 25; ++t) k[t] = kw[t];

    const float NI = __int_as_float(0xff800000u);

    float acc[5][4];
#pragma unroll
    for (int q = 0; q < 5; ++q)
#pragma unroll
        for (int c = 0; c < 4; ++c) acc[q][c] = NI;

    const float* xim = x   + (size_t)img * (IMG_H * IMG_W);
    float*       oim = out + (size_t)img * (IMG_H * IMG_W);

    // Loop-invariant column-halo validity. A covers cols j0-4..j0-1 (we use
    // j0-2,j0-1): invalid only when j0==0. C covers j0+4..j0+7 (we use
    // j0+4,j0+5): invalid only when j0==252. B (j0..j0+3) always valid.
    const bool c0ok = (j0 != 0);
    const bool c2ok = (j0 != 252);

    const float4 NIV = make_float4(NI, NI, NI, NI);
    // Double-buffered row registers; edge-lane A/C stay -inf forever.
    float4 Ab[2] = {NIV, NIV}, Bb[2] = {NIV, NIV}, Cb[2] = {NIV, NIV};

    const float* ninf = g_ninf;         // 16 floats of -inf

    int r = i0 - 2;                                          // current row
    const float* rowptr = xim + (ptrdiff_t)r * IMG_W + (j0 - 4);
    float* optr = oim + (size_t)i0 * IMG_W + j0;

    // Prologue: load row r = i0-2 into buffer 0.
    {
        const float* rp = (((unsigned)r) < (unsigned)IMG_H) ? rowptr : ninf;
        if (c0ok) Ab[0] = *(const float4*)(rp);
        Bb[0] = *(const float4*)(rp + 4);
        if (c2ok) Cb[0] = *(const float4*)(rp + 8);
    }

    // Step s (0..67), CUR = s&1, PH = s%5: prefetch row r+1 into buffer
    // CUR^1, apply row r (buffer CUR) to the 5 slots, emit output row r-2
    // once s>=4, advance.
#define DO_STEP(PH, CUR)                                                     \
    {                                                                        \
        /* prefetch next row into the other buffer */                        \
        {                                                                    \
            const int rn = r + 1;                                            \
            const float* rpn = (((unsigned)rn) < (unsigned)IMG_H)            \
                                   ? (rowptr + IMG_W) : ninf;                \
            if (c0ok) Ab[(CUR) ^ 1] = *(const float4*)(rpn);                 \
            Bb[(CUR) ^ 1] = *(const float4*)(rpn + 4);                       \
            if (c2ok) Cb[(CUR) ^ 1] = *(const float4*)(rpn + 8);             \
        }                                                                    \
        float X[12] = {Ab[CUR].x, Ab[CUR].y, Ab[CUR].z, Ab[CUR].w,           \
                       Bb[CUR].x, Bb[CUR].y, Bb[CUR].z, Bb[CUR].w,           \
                       Cb[CUR].x, Cb[CUR].y, Cb[CUR].z, Cb[CUR].w};          \
        _Pragma("unroll")                                                    \
        for (int q = 0; q < 5; ++q) {                                        \
            const int d = (q - (PH) + 5) % 5;   /* compile-time */           \
            const int u = 4 - d;                /* kernel row   */           \
            if (d == 4) {                                                    \
                _Pragma("unroll")                                            \
                for (int c = 0; c < 4; ++c)                                  \
                    acc[q][c] = X[c + 2] + k[u * 5 + 0];                     \
                _Pragma("unroll")                                            \
                for (int v = 1; v < 5; ++v)                                  \
                    _Pragma("unroll")                                        \
                    for (int c = 0; c < 4; ++c)                              \
                        acc[q][c] = fmaxf(acc[q][c], X[c + v + 2] + k[u * 5 + v]); \
            } else {                                                         \
                _Pragma("unroll")                                            \
                for (int v = 0; v < 5; ++v)                                  \
                    _Pragma("unroll")                                        \
                    for (int c = 0; c < 4; ++c)                              \
                        acc[q][c] = fmaxf(acc[q][c], X[c + v + 2] + k[u * 5 + v]); \
            }                                                                \
        }                                                                    \
        if (r >= i0 + 2) {                                                   \
            *(float4*)optr = make_float4(acc[PH][0], acc[PH][1],             \
                                         acc[PH][2], acc[PH][3]);            \
            optr += IMG_W;                                                   \
        }                                                                    \
        ++r;                                                                 \
        rowptr += IMG_W;                                                     \
    }

    // 68 steps = 6 x 10-step blocks (phase,parity cycle) + 8 remainder.
    for (int sb = 0; sb < 6; ++sb) {
        DO_STEP(0, 0) DO_STEP(1, 1) DO_STEP(2, 0) DO_STEP(3, 1) DO_STEP(4, 0)
        DO_STEP(0, 1) DO_STEP(1, 0) DO_STEP(2, 1) DO_STEP(3, 0) DO_STEP(4, 1)
    }
    // steps 60..67: phases 0,1,2,3,4,0,1,2 ; parity 0,1,0,1,0,1,0,1
    DO_STEP(0, 0) DO_STEP(1, 1) DO_STEP(2, 0) DO_STEP(3, 1) DO_STEP(4, 0)
    DO_STEP(0, 1) DO_STEP(1, 0) DO_STEP(2, 1)
#undef DO_STEP
}

extern "C" void kernel_launch(void* const* d_in, const int* in_sizes, int n_in,
                              void* d_out, int out_size) {
    const float* x  = (const float*)d_in[0];  // (16,64,256,256)
    const float* kw = (const float*)d_in[1];  // (5,5)
    float* out = (float*)d_out;
    fill_ninf_kernel<<<1, 16>>>();
    // 8192 warp-tasks = 1024 images x 4 row-strips x 2 column-halves
    dil5x5_kernel<<<2048, 128>>>(x, kw, out);
}

// round 7
// speedup vs baseline: 1.2799x; 1.0337x over previous
#include <cuda_runtime.h>
#include <cstdint>

// SemiConv2d: 5x5 max-plus dilation, 'same' padding with -inf.
// input:  (16, 64, 256, 256) fp32 -> 1024 independent 256x256 images
// kernel: (5, 5) fp32
//
// Row-streaming, 5 rotating accumulator slots, 4 cols/thread (float4 I/O),
// software-prefetched double-buffered row loads (R6 win).
// R7 change: BOUNDARY PEELING. Row-validity selects are live only in the
// first 2 / last 2 of 68 steps (strips read across strip boundaries
// legitimately; only true image edges pad). Peel 4 head + 4 tail steps;
// the 60-step steady loop has unconditional loads/stores with compile-time
// immediate offsets (ptr bump once per 10 steps), deleting ~8 integer/
// select ops per step from the binding alu pipe.

#define IMG_H 256
#define IMG_W 256

__device__ __align__(16) float g_ninf[16];

__global__ void fill_ninf_kernel() {
    g_ninf[threadIdx.x] = __int_as_float(0xff800000u);
}

__global__ void __launch_bounds__(128) dil5x5_kernel(
    const float* __restrict__ x,
    const float* __restrict__ kw,
    float* __restrict__ out)
{
    const int lane   = threadIdx.x & 31;
    const int wlocal = threadIdx.x >> 5;
    const int w      = blockIdx.x * 4 + wlocal;   // warp-task id, 0..8191

    const int img   = w >> 3;          // 0..1023
    const int strip = (w >> 1) & 3;    // 0..3  -> 64-row strip
    const int half  = w & 1;           // 0..1  -> 128-col half

    const int i0 = strip << 6;                    // first output row of strip
    const int j0 = (half << 7) + (lane << 2);     // first of 4 output cols

    float k[25];
#pragma unroll
    for (int t = 0; t < 25; ++t) k[t] = kw[t];

    const float NI = __int_as_float(0xff800000u);

    float acc[5][4];
#pragma unroll
    for (int q = 0; q < 5; ++q)
#pragma unroll
        for (int c = 0; c < 4; ++c) acc[q][c] = NI;

    const float* xim = x   + (size_t)img * (IMG_H * IMG_W);
    float*       oim = out + (size_t)img * (IMG_H * IMG_W);

    // Column-halo validity (loop-invariant). A covers cols j0-4..j0-1 (we
    // use j0-2,j0-1): invalid only when j0==0. C covers j0+4..j0+7 (we use
    // j0+4,j0+5): invalid only when j0==252. B always valid.
    const bool c0ok = (j0 != 0);
    const bool c2ok = (j0 != 252);

    // Row-halo validity: rows i0-2,i0-1 exist unless strip==0; rows
    // i0+64,i0+65 exist unless strip==3.
    const bool topok = (strip != 0);
    const bool botok = (strip != 3);

    const float4 NIV = make_float4(NI, NI, NI, NI);
    float4 Ab[2] = {NIV, NIV}, Bb[2] = {NIV, NIV}, Cb[2] = {NIV, NIV};

    const float* ninf = g_ninf;   // 16 floats of -inf

    // Load a row (base pointer at col j0-4) into buffer DSTP.
#define PREF(DSTP, RP)                                                       \
    {                                                                        \
        const float* _rp = (RP);                                             \
        if (c0ok) Ab[DSTP] = *(const float4*)(_rp);                          \
        Bb[DSTP] = *(const float4*)(_rp + 4);                                \
        if (c2ok) Cb[DSTP] = *(const float4*)(_rp + 8);                      \
    }

    // Apply buffer CUR to the 5 rotating slots (phase PH); optionally store
    // the completed slot (slot PH finishes kernel row u=4 this step).
#define MATH(PH, CUR, STOREF, OPTR)                                          \
    {                                                                        \
        float X[12] = {Ab[CUR].x, Ab[CUR].y, Ab[CUR].z, Ab[CUR].w,           \
                       Bb[CUR].x, Bb[CUR].y, Bb[CUR].z, Bb[CUR].w,           \
                       Cb[CUR].x, Cb[CUR].y, Cb[CUR].z, Cb[CUR].w};          \
        _Pragma("unroll")                                                    \
        for (int q = 0; q < 5; ++q) {                                        \
            const int d = (q - (PH) + 5) % 5;   /* compile-time */           \
            const int u = 4 - d;                /* kernel row   */           \
            if (d == 4) {                                                    \
                _Pragma("unroll")                                            \
                for (int c = 0; c < 4; ++c)                                  \
                    acc[q][c] = X[c + 2] + k[u * 5 + 0];                     \
                _Pragma("unroll")                                            \
                for (int v = 1; v < 5; ++v)                                  \
                    _Pragma("unroll")                                        \
                    for (int c = 0; c < 4; ++c)                              \
                        acc[q][c] = fmaxf(acc[q][c], X[c + v + 2] + k[u * 5 + v]); \
            } else {                                                         \
                _Pragma("unroll")                                            \
                for (int v = 0; v < 5; ++v)                                  \
                    _Pragma("unroll")                                        \
                    for (int c = 0; c < 4; ++c)                              \
                        acc[q][c] = fmaxf(acc[q][c], X[c + v + 2] + k[u * 5 + v]); \
            }                                                                \
        }                                                                    \
        if (STOREF)                                                          \
            *(float4*)(OPTR) = make_float4(acc[PH][0], acc[PH][1],           \
                                           acc[PH][2], acc[PH][3]);          \
    }

    // pbase -> row i0-2, col j0-4
    const float* pbase = xim + (ptrdiff_t)(i0 - 2) * IMG_W + (j0 - 4);

    // Prologue: buffer 0 <- row i0-2 (or -inf for strip 0).
    PREF(0, topok ? pbase : ninf)

    // Head, steps s=0..3 (consume rows i0-2..i0+1, no stores).
    // Step s: phase s%5, CUR s&1, prefetch row i0+s-1 into CUR^1.
    PREF(1, topok ? pbase + 1 * IMG_W : ninf)  MATH(0, 0, 0, oim)
    PREF(0, pbase + 2 * IMG_W)                 MATH(1, 1, 0, oim)
    PREF(1, pbase + 3 * IMG_W)                 MATH(2, 0, 0, oim)
    PREF(0, pbase + 4 * IMG_W)                 MATH(3, 1, 0, oim)

    // Steady state, steps s=4..63: all loads and stores unconditional,
    // immediate offsets, pointers bumped once per 10 steps.
    const float* pb = pbase + 5 * IMG_W;            // row i0+3 (first prefetch)
    float*       ob = oim + (size_t)i0 * IMG_W + j0; // row i0 (first store)
    for (int g = 0; g < 6; ++g) {
        PREF(1, pb + 0 * IMG_W)  MATH(4, 0, 1, ob + 0 * IMG_W)
        PREF(0, pb + 1 * IMG_W)  MATH(0, 1, 1, ob + 1 * IMG_W)
        PREF(1, pb + 2 * IMG_W)  MATH(1, 0, 1, ob + 2 * IMG_W)
        PREF(0, pb + 3 * IMG_W)  MATH(2, 1, 1, ob + 3 * IMG_W)
        PREF(1, pb + 4 * IMG_W)  MATH(3, 0, 1, ob + 4 * IMG_W)
        PREF(0, pb + 5 * IMG_W)  MATH(4, 1, 1, ob + 5 * IMG_W)
        PREF(1, pb + 6 * IMG_W)  MATH(0, 0, 1, ob + 6 * IMG_W)
        PREF(0, pb + 7 * IMG_W)  MATH(1, 1, 1, ob + 7 * IMG_W)
        PREF(1, pb + 8 * IMG_W)  MATH(2, 0, 1, ob + 8 * IMG_W)
        PREF(0, pb + 9 * IMG_W)  MATH(3, 1, 1, ob + 9 * IMG_W)
        pb += 10 * IMG_W;
        ob += 10 * IMG_W;
    }
    // After loop: pb -> row i0+63, ob -> output row i0+60.

    // Tail, steps s=64..67 (phases 4,0,1,2; CUR 0,1,0,1), prefetch rows
    // i0+63 (valid), i0+64, i0+65 (valid unless strip 3), none.
    PREF(1, pb + 0 * IMG_W)                    MATH(4, 0, 1, ob + 0 * IMG_W)
    PREF(0, botok ? pb + 1 * IMG_W : ninf)     MATH(0, 1, 1, ob + 1 * IMG_W)
    PREF(1, botok ? pb + 2 * IMG_W : ninf)     MATH(1, 0, 1, ob + 2 * IMG_W)
    /* no prefetch for the final step */       MATH(2, 1, 1, ob + 3 * IMG_W)

#undef PREF
#undef MATH
}

extern "C" void kernel_launch(void* const* d_in, const int* in_sizes, int n_in,
                              void* d_out, int out_size) {
    const float* x  = (const float*)d_in[0];  // (16,64,256,256)
    const float* kw = (const float*)d_in[1];  // (5,5)
    float* out = (float*)d_out;
    fill_ninf_kernel<<<1, 16>>>();
    // 8192 warp-tasks = 1024 images x 4 row-strips x 2 column-halves
    dil5x5_kernel<<<2048, 128>>>(x, kw, out);
}